// round 3
// baseline (speedup 1.0000x reference)
#include <cuda_runtime.h>
#include <cuda_bf16.h>
#include <cstdint>

// ---------------------------------------------------------------------------
// Problem constants
// ---------------------------------------------------------------------------
#define BATCH    2
#define TLEN     8192
#define DMODEL   768
#define DIN      1536          // d_inner
#define M_ROWS   (BATCH * TLEN)   // 16384
#define N1       (2 * DIN)        // 3072 (in_proj output)
#define CHUNK    1024
#define WARM     256              // 0.9^256 ~ 2e-12 -> exact at 1e-3 tol

// ---------------------------------------------------------------------------
// Scratch (allocation-free rule: __device__ globals)
// ---------------------------------------------------------------------------
__device__ float g_xz[(size_t)M_ROWS * N1];      // [16384, 3072]  x_inner | z
__device__ float g_y [(size_t)M_ROWS * DIN];     // [16384, 1536]  gated activations

// ---------------------------------------------------------------------------
// SGEMM: C[M,N] = A[M,K] @ B[K,N] + bias[N]   (all row-major, fp32)
// 128x128 block tile, BK=8, 256 threads, 8x8 per-thread microtile.
// M%128==0, N%128==0, K%8==0 for all our shapes -> no bounds checks.
// ---------------------------------------------------------------------------
#define BM 128
#define BN 128
#define BK 8
#define TM 8
#define TN 8

__global__ __launch_bounds__(256)
void sgemm_bias(int M, int N, int K,
                const float* __restrict__ A,
                const float* __restrict__ B,
                const float* __restrict__ bias,
                float* __restrict__ C)
{
    __shared__ float As[BK][BM];   // transposed A tile
    __shared__ float Bs[BK][BN];

    const int tid  = threadIdx.x;
    const int cRow = blockIdx.y;
    const int cCol = blockIdx.x;

    const int tRow = (tid / (BN / TN)) * TM;   // 0,8,...,120
    const int tCol = (tid % (BN / TN)) * TN;

    // global->shared load mapping
    const int aRow = tid >> 1;            // 0..127
    const int aCol = (tid & 1) * 4;       // 0 or 4
    const int bRow = tid >> 5;            // 0..7
    const int bCol = (tid & 31) * 4;      // 0..124

    const float* Ab = A + (size_t)cRow * BM * K;
    const float* Bb = B + (size_t)cCol * BN;

    float acc[TM][TN] = {};
    float ra[TM], rb[TN];

    for (int k0 = 0; k0 < K; k0 += BK) {
        float4 av = *(const float4*)(Ab + (size_t)aRow * K + k0 + aCol);
        As[aCol + 0][aRow] = av.x;
        As[aCol + 1][aRow] = av.y;
        As[aCol + 2][aRow] = av.z;
        As[aCol + 3][aRow] = av.w;

        float4 bv = *(const float4*)(Bb + (size_t)(k0 + bRow) * N + bCol);
        *(float4*)&Bs[bRow][bCol] = bv;

        __syncthreads();

        #pragma unroll
        for (int kk = 0; kk < BK; kk++) {
            #pragma unroll
            for (int i = 0; i < TM; i++) ra[i] = As[kk][tRow + i];
            #pragma unroll
            for (int j = 0; j < TN; j++) rb[j] = Bs[kk][tCol + j];
            #pragma unroll
            for (int i = 0; i < TM; i++)
                #pragma unroll
                for (int j = 0; j < TN; j++)
                    acc[i][j] = fmaf(ra[i], rb[j], acc[i][j]);
        }
        __syncthreads();
    }

    float* Cb = C + (size_t)cRow * BM * N + (size_t)cCol * BN;
    #pragma unroll
    for (int i = 0; i < TM; i++) {
        #pragma unroll
        for (int j = 0; j < TN; j += 4) {
            float4 v;
            v.x = acc[i][j + 0] + bias[cCol * BN + tCol + j + 0];
            v.y = acc[i][j + 1] + bias[cCol * BN + tCol + j + 1];
            v.z = acc[i][j + 2] + bias[cCol * BN + tCol + j + 2];
            v.w = acc[i][j + 3] + bias[cCol * BN + tCol + j + 3];
            *(float4*)(Cb + (size_t)(tRow + i) * N + tCol + j) = v;
        }
    }
}

// ---------------------------------------------------------------------------
// Fused: causal depthwise conv(4) + SiLU + EMA scan (chunked, 256-step warmup)
//        + y = (x_conv*D + h) * silu(z)
// Grid: (DIN/256, TLEN/CHUNK, BATCH). One thread = one channel within a chunk.
// Consecutive threads -> consecutive channels -> fully coalesced (stride-3072
// between timesteps, 128B-contiguous across a warp at each t).
// ---------------------------------------------------------------------------
__device__ __forceinline__ float silu_f(float v) {
    return v / (1.0f + __expf(-v));
}

__global__ __launch_bounds__(256)
void conv_scan_gate(const float* __restrict__ conv_w,   // [DIN,1,4] -> [c*4+k]
                    const float* __restrict__ conv_b,   // [DIN]
                    const float* __restrict__ D_param)  // [DIN]
{
    const int c  = blockIdx.x * blockDim.x + threadIdx.x;  // channel 0..1535
    const int t0 = blockIdx.y * CHUNK;
    const int b  = blockIdx.z;
    int ts = t0 - WARM; if (ts < 0) ts = 0;

    const float w0 = conv_w[c * 4 + 0];
    const float w1 = conv_w[c * 4 + 1];
    const float w2 = conv_w[c * 4 + 2];
    const float w3 = conv_w[c * 4 + 3];
    const float cb = conv_b[c];
    const float Dp = D_param[c];

    const float* xin = g_xz + (size_t)b * TLEN * N1 + c;        // x_inner column
    const float* zin = xin + DIN;                               // z column
    float*       yo  = g_y  + (size_t)b * TLEN * DIN + c;

    // rolling conv window (causal zero-pad at t<0)
    float xm3 = (ts - 3 >= 0) ? xin[(size_t)(ts - 3) * N1] : 0.0f;
    float xm2 = (ts - 2 >= 0) ? xin[(size_t)(ts - 2) * N1] : 0.0f;
    float xm1 = (ts - 1 >= 0) ? xin[(size_t)(ts - 1) * N1] : 0.0f;

    float h = 0.0f;
    const int tend = t0 + CHUNK;
    for (int t = ts; t < tend; t++) {
        const float xt   = xin[(size_t)t * N1];
        const float conv = fmaf(w0, xm3, fmaf(w1, xm2, fmaf(w2, xm1, fmaf(w3, xt, cb))));
        const float sc   = silu_f(conv);
        h = fmaf(0.9f, h, 0.1f * sc);
        if (t >= t0) {
            const float zv = zin[(size_t)t * N1];
            yo[(size_t)t * DIN] = fmaf(sc, Dp, h) * silu_f(zv);
        }
        xm3 = xm2; xm2 = xm1; xm1 = xt;
    }
}

// ---------------------------------------------------------------------------
// Launch
// Inputs (metadata order):
//  0 x [B,T,768] | 1 in_w [768,3072] | 2 in_b [3072] | 3 conv_w [1536,1,4]
//  4 conv_b [1536] | 5 xp_w | 6 xp_b | 7 dt_w | 8 dt_b  (5..8 dead code)
//  9 D_param [1536] | 10 out_w [1536,768] | 11 out_b [768]
// Output: [B,T,768] fp32
// ---------------------------------------------------------------------------
extern "C" void kernel_launch(void* const* d_in, const int* in_sizes, int n_in,
                              void* d_out, int out_size)
{
    (void)in_sizes; (void)n_in; (void)out_size;

    const float* x       = (const float*)d_in[0];
    const float* in_w    = (const float*)d_in[1];
    const float* in_b    = (const float*)d_in[2];
    const float* conv_w  = (const float*)d_in[3];
    const float* conv_b  = (const float*)d_in[4];
    const float* D_param = (const float*)d_in[9];
    const float* out_w   = (const float*)d_in[10];
    const float* out_b   = (const float*)d_in[11];
    float*       out     = (float*)d_out;

    float* xz = nullptr;
    float* ya = nullptr;
    cudaGetSymbolAddress((void**)&xz, g_xz);
    cudaGetSymbolAddress((void**)&ya, g_y);

    // GEMM1: xz[16384,3072] = x[16384,768] @ in_w[768,3072] + in_b
    {
        dim3 grid(N1 / BN, M_ROWS / BM);
        sgemm_bias<<<grid, 256>>>(M_ROWS, N1, DMODEL, x, in_w, in_b, xz);
    }

    // Fused conv + silu + EMA scan + gate -> g_y
    {
        dim3 grid(DIN / 256, TLEN / CHUNK, BATCH);
        conv_scan_gate<<<grid, 256>>>(conv_w, conv_b, D_param);
    }

    // GEMM2: out[16384,768] = y[16384,1536] @ out_w[1536,768] + out_b
    {
        dim3 grid(DMODEL / BN, M_ROWS / BM);
        sgemm_bias<<<grid, 256>>>(M_ROWS, DMODEL, DIN, ya, out_w, out_b, out);
    }
}

// round 5
// speedup vs baseline: 1.8886x; 1.8886x over previous
#include <cuda_runtime.h>
#include <cuda_bf16.h>
#include <cstdint>

// ---------------------------------------------------------------------------
// Problem constants
// ---------------------------------------------------------------------------
#define BATCH    2
#define TLEN     8192
#define DMODEL   768
#define DIN      1536
#define M_ROWS   (BATCH * TLEN)   // 16384
#define N1       (2 * DIN)        // 3072
#define CHUNK    1024
#define WARM     256              // 0.9^256 ~ 2e-12 -> exact at 1e-3 tol

// ---------------------------------------------------------------------------
// Scratch
// ---------------------------------------------------------------------------
__device__ float g_xz[(size_t)M_ROWS * N1];      // [16384, 3072]  x_inner | z
__device__ float g_y [(size_t)M_ROWS * DIN];     // [16384, 1536]

// ---------------------------------------------------------------------------
// TF32 tensor-core GEMM: C[M,N] = A[M,K] @ B[K,N] + bias[N]  (row-major fp32)
// 128x128x32 CTA tile, 256 thr (8 warps, 4x2), warp tile 32x64,
// mma.sync.m16n8k8.tf32, cp.async double-buffered smem pipeline.
// Requires M%128==0, N%128==0, K%32==0 (true for all our shapes).
// ---------------------------------------------------------------------------
#define BM 128
#define BN 128
#define BK 32
#define BKP 36            // padded A row stride (words) -> conflict-free frags
#define BNP 132           // padded B row stride
#define AS_SZ (BM * BKP)  // 4608 floats per A buffer
#define BS_SZ (BK * BNP)  // 4224 floats per B buffer
#define BS_OFF (2 * AS_SZ)
#define SMEM_FLOATS (2 * AS_SZ + 2 * BS_SZ)   // 17664 floats = 70656 B

__device__ __forceinline__ void cp16(float* smem_ptr, const float* g) {
    uint32_t a = (uint32_t)__cvta_generic_to_shared(smem_ptr);
    asm volatile("cp.async.cg.shared.global [%0], [%1], 16;" :: "r"(a), "l"(g));
}
__device__ __forceinline__ uint32_t f2tf(float v) {
    uint32_t r;
    asm("cvt.rna.tf32.f32 %0, %1;" : "=r"(r) : "f"(v));
    return r;
}

__global__ __launch_bounds__(256, 2)
void tf32_gemm_bias(int M, int N, int K,
                    const float* __restrict__ A,
                    const float* __restrict__ B,
                    const float* __restrict__ bias,
                    float* __restrict__ C)
{
    extern __shared__ float sm[];

    const int tid  = threadIdx.x;
    const int lane = tid & 31;
    const int wid  = tid >> 5;
    const int g    = lane >> 2;       // 0..7
    const int c    = lane & 3;        // 0..3
    const int wm   = wid & 3;         // warp row 0..3  (32 rows each)
    const int wn   = wid >> 2;        // warp col 0..1  (64 cols each)

    const int cRow = blockIdx.y;
    const int cCol = blockIdx.x;
    const float* Ab = A + (size_t)cRow * BM * K;
    const float* Bb = B + (size_t)cCol * BN;

    // global->smem load mapping (per pass: 256 thr x float4 = 1024 floats)
    const int aR = tid >> 3;          // 0..31 (row within pass group)
    const int aK = (tid & 7) * 4;     // 0..28
    const int bKr = tid >> 6;         // 0..3  (k-row within pass group of 8? -> use tid>>5)
    (void)bKr;
    const int bK = tid >> 5;          // 0..7
    const int bN = (tid & 31) * 4;    // 0..124

    float acc[2][8][4];
    #pragma unroll
    for (int i = 0; i < 2; i++)
        #pragma unroll
        for (int j = 0; j < 8; j++)
            #pragma unroll
            for (int q = 0; q < 4; q++) acc[i][j][q] = 0.0f;

    const int iters = K / BK;

    // ---- issue loads for tile 0 ----
    {
        const int k0 = 0, buf = 0;
        #pragma unroll
        for (int p = 0; p < 4; p++) {
            int row = p * 32 + aR;
            cp16(&sm[buf * AS_SZ + row * BKP + aK], Ab + (size_t)row * K + k0 + aK);
        }
        #pragma unroll
        for (int p = 0; p < 4; p++) {
            int kr = p * 8 + bK;
            cp16(&sm[BS_OFF + buf * BS_SZ + kr * BNP + bN], Bb + (size_t)(k0 + kr) * N + bN);
        }
        asm volatile("cp.async.commit_group;");
    }

    for (int it = 0; it < iters; it++) {
        const int buf = it & 1;

        if (it + 1 < iters) {
            const int k0 = (it + 1) * BK, nb = (it + 1) & 1;
            #pragma unroll
            for (int p = 0; p < 4; p++) {
                int row = p * 32 + aR;
                cp16(&sm[nb * AS_SZ + row * BKP + aK], Ab + (size_t)row * K + k0 + aK);
            }
            #pragma unroll
            for (int p = 0; p < 4; p++) {
                int kr = p * 8 + bK;
                cp16(&sm[BS_OFF + nb * BS_SZ + kr * BNP + bN], Bb + (size_t)(k0 + kr) * N + bN);
            }
            asm volatile("cp.async.commit_group;");
            asm volatile("cp.async.wait_group 1;");
        } else {
            asm volatile("cp.async.wait_group 0;");
        }
        __syncthreads();

        const float* AsP = sm + buf * AS_SZ + (wm * 32) * BKP;
        const float* BsP = sm + BS_OFF + buf * BS_SZ + wn * 64;

        #pragma unroll
        for (int ks = 0; ks < 4; ks++) {
            const int kk = ks * 8;

            uint32_t af[2][4];
            #pragma unroll
            for (int i = 0; i < 2; i++) {
                const int r = i * 16 + g;
                af[i][0] = f2tf(AsP[(size_t)r * BKP + kk + c]);
                af[i][1] = f2tf(AsP[(size_t)(r + 8) * BKP + kk + c]);
                af[i][2] = f2tf(AsP[(size_t)r * BKP + kk + c + 4]);
                af[i][3] = f2tf(AsP[(size_t)(r + 8) * BKP + kk + c + 4]);
            }
            uint32_t bf[8][2];
            #pragma unroll
            for (int j = 0; j < 8; j++) {
                bf[j][0] = f2tf(BsP[(size_t)(kk + c) * BNP + j * 8 + g]);
                bf[j][1] = f2tf(BsP[(size_t)(kk + c + 4) * BNP + j * 8 + g]);
            }
            #pragma unroll
            for (int i = 0; i < 2; i++)
                #pragma unroll
                for (int j = 0; j < 8; j++) {
                    asm volatile(
                        "mma.sync.aligned.m16n8k8.row.col.f32.tf32.tf32.f32 "
                        "{%0,%1,%2,%3}, {%4,%5,%6,%7}, {%8,%9}, {%0,%1,%2,%3};"
                        : "+f"(acc[i][j][0]), "+f"(acc[i][j][1]),
                          "+f"(acc[i][j][2]), "+f"(acc[i][j][3])
                        : "r"(af[i][0]), "r"(af[i][1]), "r"(af[i][2]), "r"(af[i][3]),
                          "r"(bf[j][0]), "r"(bf[j][1]));
                }
        }
        __syncthreads();
    }

    // ---- epilogue: add bias, write C ----
    #pragma unroll
    for (int i = 0; i < 2; i++) {
        #pragma unroll
        for (int j = 0; j < 8; j++) {
            const int row = cRow * BM + wm * 32 + i * 16 + g;
            const int col = cCol * BN + wn * 64 + j * 8 + 2 * c;
            const float bx = bias[col];
            const float by = bias[col + 1];
            float2 v0 = make_float2(acc[i][j][0] + bx, acc[i][j][1] + by);
            float2 v1 = make_float2(acc[i][j][2] + bx, acc[i][j][3] + by);
            *(float2*)&C[(size_t)row * N + col]       = v0;
            *(float2*)&C[(size_t)(row + 8) * N + col] = v1;
        }
    }
}

// ---------------------------------------------------------------------------
// Fused conv(4) + SiLU + chunked EMA scan + gating (unchanged, passing)
// ---------------------------------------------------------------------------
__device__ __forceinline__ float silu_f(float v) {
    return v / (1.0f + __expf(-v));
}

__global__ __launch_bounds__(256)
void conv_scan_gate(const float* __restrict__ conv_w,
                    const float* __restrict__ conv_b,
                    const float* __restrict__ D_param)
{
    const int c  = blockIdx.x * blockDim.x + threadIdx.x;
    const int t0 = blockIdx.y * CHUNK;
    const int b  = blockIdx.z;
    int ts = t0 - WARM; if (ts < 0) ts = 0;

    const float w0 = conv_w[c * 4 + 0];
    const float w1 = conv_w[c * 4 + 1];
    const float w2 = conv_w[c * 4 + 2];
    const float w3 = conv_w[c * 4 + 3];
    const float cb = conv_b[c];
    const float Dp = D_param[c];

    const float* xin = g_xz + (size_t)b * TLEN * N1 + c;
    const float* zin = xin + DIN;
    float*       yo  = g_y  + (size_t)b * TLEN * DIN + c;

    float xm3 = (ts - 3 >= 0) ? xin[(size_t)(ts - 3) * N1] : 0.0f;
    float xm2 = (ts - 2 >= 0) ? xin[(size_t)(ts - 2) * N1] : 0.0f;
    float xm1 = (ts - 1 >= 0) ? xin[(size_t)(ts - 1) * N1] : 0.0f;

    float h = 0.0f;
    const int tend = t0 + CHUNK;
    for (int t = ts; t < tend; t++) {
        const float xt   = xin[(size_t)t * N1];
        const float conv = fmaf(w0, xm3, fmaf(w1, xm2, fmaf(w2, xm1, fmaf(w3, xt, cb))));
        const float sc   = silu_f(conv);
        h = fmaf(0.9f, h, 0.1f * sc);
        if (t >= t0) {
            const float zv = zin[(size_t)t * N1];
            yo[(size_t)t * DIN] = fmaf(sc, Dp, h) * silu_f(zv);
        }
        xm3 = xm2; xm2 = xm1; xm1 = xt;
    }
}

// ---------------------------------------------------------------------------
// Launch
// ---------------------------------------------------------------------------
extern "C" void kernel_launch(void* const* d_in, const int* in_sizes, int n_in,
                              void* d_out, int out_size)
{
    (void)in_sizes; (void)n_in; (void)out_size;

    const float* x       = (const float*)d_in[0];
    const float* in_w    = (const float*)d_in[1];
    const float* in_b    = (const float*)d_in[2];
    const float* conv_w  = (const float*)d_in[3];
    const float* conv_b  = (const float*)d_in[4];
    const float* D_param = (const float*)d_in[9];
    const float* out_w   = (const float*)d_in[10];
    const float* out_b   = (const float*)d_in[11];
    float*       out     = (float*)d_out;

    float* xz = nullptr;
    float* ya = nullptr;
    cudaGetSymbolAddress((void**)&xz, g_xz);
    cudaGetSymbolAddress((void**)&ya, g_y);

    static bool attr_set = false;
    const int smem_bytes = SMEM_FLOATS * (int)sizeof(float);  // 70656
    if (!attr_set) {
        cudaFuncSetAttribute(tf32_gemm_bias,
                             cudaFuncAttributeMaxDynamicSharedMemorySize, smem_bytes);
        attr_set = true;
    }

    // GEMM1: xz[16384,3072] = x @ in_w + in_b
    {
        dim3 grid(N1 / BN, M_ROWS / BM);
        tf32_gemm_bias<<<grid, 256, smem_bytes>>>(M_ROWS, N1, DMODEL, x, in_w, in_b, xz);
    }

    // Fused conv + silu + EMA scan + gate -> g_y
    {
        dim3 grid(DIN / 256, TLEN / CHUNK, BATCH);
        conv_scan_gate<<<grid, 256>>>(conv_w, conv_b, D_param);
    }

    // GEMM2: out[16384,768] = y @ out_w + out_b
    {
        dim3 grid(DMODEL / BN, M_ROWS / BM);
        tf32_gemm_bias<<<grid, 256, smem_bytes>>>(M_ROWS, DMODEL, DIN, ya, out_w, out_b, out);
    }
}

// round 6
// speedup vs baseline: 2.6502x; 1.4033x over previous
#include <cuda_runtime.h>
#include <cuda_bf16.h>
#include <cstdint>

// ---------------------------------------------------------------------------
// Problem constants
// ---------------------------------------------------------------------------
#define BATCH    2
#define TLEN     8192
#define DMODEL   768
#define DIN      1536
#define M_ROWS   (BATCH * TLEN)   // 16384
#define N1       (2 * DIN)        // 3072
#define CHUNK    512
#define WARM     160              // 0.9^160 ~ 5e-8 -> exact at 1e-3 tol

// ---------------------------------------------------------------------------
// Scratch (__device__ globals; no allocation allowed)
// ---------------------------------------------------------------------------
__device__ float g_xz[(size_t)M_ROWS * N1];      // [16384, 3072]  x_inner | z
__device__ float g_y [(size_t)M_ROWS * DIN];     // [16384, 1536]  (tf32-rounded)
__device__ float g_xr[(size_t)M_ROWS * DMODEL];  // x pre-rounded to tf32
__device__ float g_w1[(size_t)DMODEL * N1];      // in_w pre-rounded
__device__ float g_w2[(size_t)DIN * DMODEL];     // out_w pre-rounded

__device__ __forceinline__ uint32_t f2tf(float v) {
    uint32_t r;
    asm("cvt.rna.tf32.f32 %0, %1;" : "=r"(r) : "f"(v));
    return r;
}

// ---------------------------------------------------------------------------
// Elementwise tf32 pre-rounding (bitwise identical to in-GEMM cvt.rna)
// ---------------------------------------------------------------------------
__global__ __launch_bounds__(256)
void round_tf32(const float4* __restrict__ in, float4* __restrict__ out, int n4)
{
    int i = blockIdx.x * blockDim.x + threadIdx.x;
    if (i < n4) {
        float4 v = in[i];
        v.x = __uint_as_float(f2tf(v.x));
        v.y = __uint_as_float(f2tf(v.y));
        v.z = __uint_as_float(f2tf(v.z));
        v.w = __uint_as_float(f2tf(v.w));
        out[i] = v;
    }
}

// ---------------------------------------------------------------------------
// TF32 tensor-core GEMM (pre-rounded operands): C = A @ B + bias
// 128x128x32 CTA tile, 256 thr (4x2 warps, 32x64 warp tile),
// mma.sync.m16n8k8.tf32, cp.async double-buffered. No cvt in mainloop.
// ---------------------------------------------------------------------------
#define BM 128
#define BN 128
#define BK 32
#define BKP 36
#define BNP 132
#define AS_SZ (BM * BKP)
#define BS_SZ (BK * BNP)
#define BS_OFF (2 * AS_SZ)
#define SMEM_FLOATS (2 * AS_SZ + 2 * BS_SZ)   // 70656 B

__device__ __forceinline__ void cp16(float* smem_ptr, const float* g) {
    uint32_t a = (uint32_t)__cvta_generic_to_shared(smem_ptr);
    asm volatile("cp.async.cg.shared.global [%0], [%1], 16;" :: "r"(a), "l"(g));
}

__global__ __launch_bounds__(256, 2)
void tf32_gemm_bias(int M, int N, int K,
                    const float* __restrict__ A,
                    const float* __restrict__ B,
                    const float* __restrict__ bias,
                    float* __restrict__ C)
{
    extern __shared__ float sm[];

    const int tid  = threadIdx.x;
    const int lane = tid & 31;
    const int wid  = tid >> 5;
    const int g    = lane >> 2;       // 0..7
    const int c    = lane & 3;        // 0..3
    const int wm   = wid & 3;         // warp row (32 rows)
    const int wn   = wid >> 2;        // warp col (64 cols)

    const int cRow = blockIdx.y;
    const int cCol = blockIdx.x;
    const float* Ab = A + (size_t)cRow * BM * K;
    const float* Bb = B + (size_t)cCol * BN;

    const int aR = tid >> 3;          // 0..31
    const int aK = (tid & 7) * 4;     // 0..28
    const int bK = tid >> 5;          // 0..7
    const int bN = (tid & 31) * 4;    // 0..124

    float acc[2][8][4];
    #pragma unroll
    for (int i = 0; i < 2; i++)
        #pragma unroll
        for (int j = 0; j < 8; j++)
            #pragma unroll
            for (int q = 0; q < 4; q++) acc[i][j][q] = 0.0f;

    const int iters = K / BK;

    {
        #pragma unroll
        for (int p = 0; p < 4; p++) {
            int row = p * 32 + aR;
            cp16(&sm[row * BKP + aK], Ab + (size_t)row * K + aK);
        }
        #pragma unroll
        for (int p = 0; p < 4; p++) {
            int kr = p * 8 + bK;
            cp16(&sm[BS_OFF + kr * BNP + bN], Bb + (size_t)kr * N + bN);
        }
        asm volatile("cp.async.commit_group;");
    }

    for (int it = 0; it < iters; it++) {
        const int buf = it & 1;

        if (it + 1 < iters) {
            const int k0 = (it + 1) * BK, nb = (it + 1) & 1;
            #pragma unroll
            for (int p = 0; p < 4; p++) {
                int row = p * 32 + aR;
                cp16(&sm[nb * AS_SZ + row * BKP + aK], Ab + (size_t)row * K + k0 + aK);
            }
            #pragma unroll
            for (int p = 0; p < 4; p++) {
                int kr = p * 8 + bK;
                cp16(&sm[BS_OFF + nb * BS_SZ + kr * BNP + bN], Bb + (size_t)(k0 + kr) * N + bN);
            }
            asm volatile("cp.async.commit_group;");
            asm volatile("cp.async.wait_group 1;");
        } else {
            asm volatile("cp.async.wait_group 0;");
        }
        __syncthreads();

        const uint32_t* AsP = (const uint32_t*)(sm + buf * AS_SZ) + (wm * 32) * BKP;
        const uint32_t* BsP = (const uint32_t*)(sm + BS_OFF + buf * BS_SZ) + wn * 64;

        #pragma unroll
        for (int ks = 0; ks < 4; ks++) {
            const int kk = ks * 8;

            uint32_t af[2][4];
            #pragma unroll
            for (int i = 0; i < 2; i++) {
                const int r = i * 16 + g;
                af[i][0] = AsP[r * BKP + kk + c];
                af[i][1] = AsP[(r + 8) * BKP + kk + c];
                af[i][2] = AsP[r * BKP + kk + c + 4];
                af[i][3] = AsP[(r + 8) * BKP + kk + c + 4];
            }
            uint32_t bf[8][2];
            #pragma unroll
            for (int j = 0; j < 8; j++) {
                bf[j][0] = BsP[(kk + c) * BNP + j * 8 + g];
                bf[j][1] = BsP[(kk + c + 4) * BNP + j * 8 + g];
            }
            #pragma unroll
            for (int i = 0; i < 2; i++)
                #pragma unroll
                for (int j = 0; j < 8; j++) {
                    asm volatile(
                        "mma.sync.aligned.m16n8k8.row.col.f32.tf32.tf32.f32 "
                        "{%0,%1,%2,%3}, {%4,%5,%6,%7}, {%8,%9}, {%0,%1,%2,%3};"
                        : "+f"(acc[i][j][0]), "+f"(acc[i][j][1]),
                          "+f"(acc[i][j][2]), "+f"(acc[i][j][3])
                        : "r"(af[i][0]), "r"(af[i][1]), "r"(af[i][2]), "r"(af[i][3]),
                          "r"(bf[j][0]), "r"(bf[j][1]));
                }
        }
        __syncthreads();
    }

    #pragma unroll
    for (int i = 0; i < 2; i++) {
        #pragma unroll
        for (int j = 0; j < 8; j++) {
            const int row = cRow * BM + wm * 32 + i * 16 + g;
            const int col = cCol * BN + wn * 64 + j * 8 + 2 * c;
            const float bx = bias[col];
            const float by = bias[col + 1];
            float2 v0 = make_float2(acc[i][j][0] + bx, acc[i][j][1] + by);
            float2 v1 = make_float2(acc[i][j][2] + bx, acc[i][j][3] + by);
            *(float2*)&C[(size_t)row * N + col]       = v0;
            *(float2*)&C[(size_t)(row + 8) * N + col] = v1;
        }
    }
}

// ---------------------------------------------------------------------------
// Fused conv(4) + SiLU + chunked EMA scan + gating.
// CHUNK=512, WARM=160, blockDim=128 -> 384 CTAs (was 96).
// Output stored tf32-rounded (identical bits to in-GEMM cvt).
// ---------------------------------------------------------------------------
__device__ __forceinline__ float silu_f(float v) {
    return v / (1.0f + __expf(-v));
}

__global__ __launch_bounds__(128)
void conv_scan_gate(const float* __restrict__ conv_w,
                    const float* __restrict__ conv_b,
                    const float* __restrict__ D_param)
{
    const int c  = blockIdx.x * blockDim.x + threadIdx.x;
    const int t0 = blockIdx.y * CHUNK;
    const int b  = blockIdx.z;
    int ts = t0 - WARM; if (ts < 0) ts = 0;

    const float w0 = conv_w[c * 4 + 0];
    const float w1 = conv_w[c * 4 + 1];
    const float w2 = conv_w[c * 4 + 2];
    const float w3 = conv_w[c * 4 + 3];
    const float cb = conv_b[c];
    const float Dp = D_param[c];

    const float* xin = g_xz + (size_t)b * TLEN * N1 + c;
    const float* zin = xin + DIN;
    float*       yo  = g_y  + (size_t)b * TLEN * DIN + c;

    float xm3 = (ts - 3 >= 0) ? xin[(size_t)(ts - 3) * N1] : 0.0f;
    float xm2 = (ts - 2 >= 0) ? xin[(size_t)(ts - 2) * N1] : 0.0f;
    float xm1 = (ts - 1 >= 0) ? xin[(size_t)(ts - 1) * N1] : 0.0f;

    float h = 0.0f;
    const int tend = t0 + CHUNK;
    #pragma unroll 4
    for (int t = ts; t < tend; t++) {
        const float xt   = xin[(size_t)t * N1];
        const float conv = fmaf(w0, xm3, fmaf(w1, xm2, fmaf(w2, xm1, fmaf(w3, xt, cb))));
        const float sc   = silu_f(conv);
        h = fmaf(0.9f, h, 0.1f * sc);
        if (t >= t0) {
            const float zv = zin[(size_t)t * N1];
            const float yv = fmaf(sc, Dp, h) * silu_f(zv);
            yo[(size_t)t * DIN] = __uint_as_float(f2tf(yv));
        }
        xm3 = xm2; xm2 = xm1; xm1 = xt;
    }
}

// ---------------------------------------------------------------------------
// Launch
// ---------------------------------------------------------------------------
extern "C" void kernel_launch(void* const* d_in, const int* in_sizes, int n_in,
                              void* d_out, int out_size)
{
    (void)in_sizes; (void)n_in; (void)out_size;

    const float* x       = (const float*)d_in[0];
    const float* in_w    = (const float*)d_in[1];
    const float* in_b    = (const float*)d_in[2];
    const float* conv_w  = (const float*)d_in[3];
    const float* conv_b  = (const float*)d_in[4];
    const float* D_param = (const float*)d_in[9];
    const float* out_w   = (const float*)d_in[10];
    const float* out_b   = (const float*)d_in[11];
    float*       out     = (float*)d_out;

    float *xz, *ya, *xr, *w1, *w2;
    cudaGetSymbolAddress((void**)&xz, g_xz);
    cudaGetSymbolAddress((void**)&ya, g_y);
    cudaGetSymbolAddress((void**)&xr, g_xr);
    cudaGetSymbolAddress((void**)&w1, g_w1);
    cudaGetSymbolAddress((void**)&w2, g_w2);

    static bool attr_set = false;
    const int smem_bytes = SMEM_FLOATS * (int)sizeof(float);  // 70656
    if (!attr_set) {
        cudaFuncSetAttribute(tf32_gemm_bias,
                             cudaFuncAttributeMaxDynamicSharedMemorySize, smem_bytes);
        attr_set = true;
    }

    // Pre-round A/B operands to tf32 (bitwise identical to in-GEMM cvt.rna)
    {
        int n4;
        n4 = (M_ROWS * DMODEL) / 4;
        round_tf32<<<(n4 + 255) / 256, 256>>>((const float4*)x, (float4*)xr, n4);
        n4 = (DMODEL * N1) / 4;
        round_tf32<<<(n4 + 255) / 256, 256>>>((const float4*)in_w, (float4*)w1, n4);
        n4 = (DIN * DMODEL) / 4;
        round_tf32<<<(n4 + 255) / 256, 256>>>((const float4*)out_w, (float4*)w2, n4);
    }

    // GEMM1: xz[16384,3072] = xr @ w1 + in_b
    {
        dim3 grid(N1 / BN, M_ROWS / BM);
        tf32_gemm_bias<<<grid, 256, smem_bytes>>>(M_ROWS, N1, DMODEL, xr, w1, in_b, xz);
    }

    // Fused conv + silu + EMA scan + gate -> g_y (tf32-rounded)
    {
        dim3 grid(DIN / 128, TLEN / CHUNK, BATCH);
        conv_scan_gate<<<grid, 128>>>(conv_w, conv_b, D_param);
    }

    // GEMM2: out[16384,768] = y @ w2 + out_b
    {
        dim3 grid(DMODEL / BN, M_ROWS / BM);
        tf32_gemm_bias<<<grid, 256, smem_bytes>>>(M_ROWS, DMODEL, DIN, ya, w2, out_b, out);
    }
}

// round 7
// speedup vs baseline: 3.6798x; 1.3885x over previous
#include <cuda_runtime.h>
#include <cuda_bf16.h>
#include <cstdint>

// ---------------------------------------------------------------------------
// Problem constants
// ---------------------------------------------------------------------------
#define BATCH    2
#define TLEN     8192
#define DMODEL   768
#define DIN      1536
#define M_ROWS   (BATCH * TLEN)   // 16384
#define N1       (2 * DIN)        // 3072
#define CHUNK    256
#define WARM     128              // 0.9^128 ~ 1.4e-6 -> exact at 1e-3 tol

// ---------------------------------------------------------------------------
// Scratch (__device__ globals; no allocation allowed)
// ---------------------------------------------------------------------------
__device__ float g_xz [(size_t)M_ROWS * N1];      // [16384, 3072]  x_inner | z
__device__ float g_y  [(size_t)M_ROWS * DIN];     // [16384, 1536]  (tf32-rounded)
__device__ float g_xr [(size_t)M_ROWS * DMODEL];  // x pre-rounded to tf32
__device__ float g_w1t[(size_t)N1 * DMODEL];      // in_w^T  [3072][768], tf32-rounded
__device__ float g_w2t[(size_t)DMODEL * DIN];     // out_w^T [768][1536], tf32-rounded

__device__ __forceinline__ uint32_t f2tf(float v) {
    uint32_t r;
    asm("cvt.rna.tf32.f32 %0, %1;" : "=r"(r) : "f"(v));
    return r;
}

// ---------------------------------------------------------------------------
// Prepass 1: elementwise tf32 rounding (for x)
// ---------------------------------------------------------------------------
__global__ __launch_bounds__(256)
void round_tf32(const float4* __restrict__ in, float4* __restrict__ out, int n4)
{
    int i = blockIdx.x * blockDim.x + threadIdx.x;
    if (i < n4) {
        float4 v = in[i];
        v.x = __uint_as_float(f2tf(v.x));
        v.y = __uint_as_float(f2tf(v.y));
        v.z = __uint_as_float(f2tf(v.z));
        v.w = __uint_as_float(f2tf(v.w));
        out[i] = v;
    }
}

// ---------------------------------------------------------------------------
// Prepass 2: transpose + tf32 round.  in[R][C] -> out[C][R]
// block (32,8), grid (C/32, R/32). R,C multiples of 32.
// ---------------------------------------------------------------------------
__global__ __launch_bounds__(256)
void transpose_round(const float* __restrict__ in, float* __restrict__ out,
                     int R, int C)
{
    __shared__ float t[32][33];
    const int bx = blockIdx.x * 32;   // col base in `in`
    const int by = blockIdx.y * 32;   // row base in `in`
    const int tx = threadIdx.x, ty = threadIdx.y;

    #pragma unroll
    for (int dy = 0; dy < 32; dy += 8)
        t[ty + dy][tx] = in[(size_t)(by + ty + dy) * C + bx + tx];
    __syncthreads();
    #pragma unroll
    for (int dy = 0; dy < 32; dy += 8)
        out[(size_t)(bx + ty + dy) * R + by + tx] =
            __uint_as_float(f2tf(t[tx][ty + dy]));
}

// ---------------------------------------------------------------------------
// TF32 tensor-core GEMM with ldmatrix fragment loads.
//   C[M,N] = A[M,K] @ B[K,N] + bias[N],  B passed TRANSPOSED as BT[N][K].
// 128x128x32 CTA tile, 256 thr (4x2 warps, 32x64 warp tiles),
// mma.sync.m16n8k8.tf32, cp.async double-buffered, LDSM.x4 fragments.
// A and BT smem tiles share the same [128 rows][32 k] layout, stride 36.
// ---------------------------------------------------------------------------
#define BM 128
#define BN 128
#define BK 32
#define BKP 36                      // padded row stride (words) -> LDSM conflict-free
#define AS_SZ (BM * BKP)            // 4608 floats / buffer
#define BS_SZ (BN * BKP)            // 4608 floats / buffer
#define BS_OFF (2 * AS_SZ)
#define SMEM_FLOATS (2 * AS_SZ + 2 * BS_SZ)   // 18432 floats = 73728 B
#define AS_SZB (AS_SZ * 4)
#define BS_SZB (BS_SZ * 4)
#define BS_OFFB (BS_OFF * 4)
#define ROWB (BKP * 4)              // 144 bytes per smem row

__device__ __forceinline__ void cp16(float* smem_ptr, const float* g) {
    uint32_t a = (uint32_t)__cvta_generic_to_shared(smem_ptr);
    asm volatile("cp.async.cg.shared.global [%0], [%1], 16;" :: "r"(a), "l"(g));
}
__device__ __forceinline__ void ldsm4(uint32_t& r0, uint32_t& r1,
                                      uint32_t& r2, uint32_t& r3, uint32_t addr) {
    asm volatile("ldmatrix.sync.aligned.m8n8.x4.shared.b16 {%0,%1,%2,%3}, [%4];"
                 : "=r"(r0), "=r"(r1), "=r"(r2), "=r"(r3) : "r"(addr));
}

__global__ __launch_bounds__(256, 2)
void tf32_gemm_bias(int M, int N, int K,
                    const float* __restrict__ A,
                    const float* __restrict__ BT,
                    const float* __restrict__ bias,
                    float* __restrict__ C)
{
    extern __shared__ float sm[];

    const int tid  = threadIdx.x;
    const int lane = tid & 31;
    const int wid  = tid >> 5;
    const int g    = lane >> 2;
    const int c    = lane & 3;
    const int wm   = wid & 3;          // warp row (32 rows)
    const int wn   = wid >> 2;         // warp col (64 cols)

    const int cRow = blockIdx.y;
    const int cCol = blockIdx.x;
    const float* Ab = A  + (size_t)cRow * BM * K;
    const float* Bb = BT + (size_t)cCol * BN * K;   // BT rows = n, stride K

    // cp.async mapping (identical for A and BT): 32 rows x 32 k per pass
    const int aR = tid >> 3;           // 0..31
    const int aK = (tid & 7) * 4;      // 0..28

    // LDSM per-thread byte offsets within a buffer
    const uint32_t smem_u = (uint32_t)__cvta_generic_to_shared(sm);
    // A: lanes 0-15 -> rows 0..15 (k lo/…), lanes 16-31 -> same rows, k+4
    const uint32_t a_off = (uint32_t)((wm * 32 + (lane & 15)) * ROWB + (lane >> 4) * 16);
    // B: row-in-16-group = (lane&7) + ((lane>>4)<<3); k half = ((lane>>3)&1)*4
    const uint32_t b_off = (uint32_t)((wn * 64 + ((lane & 7) + ((lane >> 4) << 3))) * ROWB
                                      + (((lane >> 3) & 1) << 4));

    float acc[2][8][4];
    #pragma unroll
    for (int i = 0; i < 2; i++)
        #pragma unroll
        for (int j = 0; j < 8; j++)
            #pragma unroll
            for (int q = 0; q < 4; q++) acc[i][j][q] = 0.0f;

    const int iters = K / BK;

    {   // prologue: tile 0
        #pragma unroll
        for (int p = 0; p < 4; p++) {
            const int row = p * 32 + aR;
            cp16(&sm[row * BKP + aK],          Ab + (size_t)row * K + aK);
            cp16(&sm[BS_OFF + row * BKP + aK], Bb + (size_t)row * K + aK);
        }
        asm volatile("cp.async.commit_group;");
    }

    for (int it = 0; it < iters; it++) {
        const int buf = it & 1;

        if (it + 1 < iters) {
            const int k0 = (it + 1) * BK, nb = (it + 1) & 1;
            #pragma unroll
            for (int p = 0; p < 4; p++) {
                const int row = p * 32 + aR;
                cp16(&sm[nb * AS_SZ + row * BKP + aK],
                     Ab + (size_t)row * K + k0 + aK);
                cp16(&sm[BS_OFF + nb * BS_SZ + row * BKP + aK],
                     Bb + (size_t)row * K + k0 + aK);
            }
            asm volatile("cp.async.commit_group;");
            asm volatile("cp.async.wait_group 1;");
        } else {
            asm volatile("cp.async.wait_group 0;");
        }
        __syncthreads();

        const uint32_t aBase = smem_u + (uint32_t)buf * AS_SZB + a_off;
        const uint32_t bBase = smem_u + BS_OFFB + (uint32_t)buf * BS_SZB + b_off;

        #pragma unroll
        for (int ks = 0; ks < 4; ks++) {
            const uint32_t kb = (uint32_t)ks * 32;   // ks*8 floats = 32 bytes

            uint32_t af[2][4];
            ldsm4(af[0][0], af[0][1], af[0][2], af[0][3], aBase + kb);
            ldsm4(af[1][0], af[1][1], af[1][2], af[1][3], aBase + 16 * ROWB + kb);

            uint32_t bf[8][2];
            #pragma unroll
            for (int j2 = 0; j2 < 4; j2++) {
                uint32_t r0, r1, r2, r3;
                ldsm4(r0, r1, r2, r3, bBase + (uint32_t)j2 * 16 * ROWB + kb);
                bf[2 * j2][0]     = r0;  bf[2 * j2][1]     = r1;
                bf[2 * j2 + 1][0] = r2;  bf[2 * j2 + 1][1] = r3;
            }

            #pragma unroll
            for (int i = 0; i < 2; i++)
                #pragma unroll
                for (int j = 0; j < 8; j++) {
                    asm volatile(
                        "mma.sync.aligned.m16n8k8.row.col.f32.tf32.tf32.f32 "
                        "{%0,%1,%2,%3}, {%4,%5,%6,%7}, {%8,%9}, {%0,%1,%2,%3};"
                        : "+f"(acc[i][j][0]), "+f"(acc[i][j][1]),
                          "+f"(acc[i][j][2]), "+f"(acc[i][j][3])
                        : "r"(af[i][0]), "r"(af[i][1]), "r"(af[i][2]), "r"(af[i][3]),
                          "r"(bf[j][0]), "r"(bf[j][1]));
                }
        }
        __syncthreads();
    }

    // epilogue: bias + store
    #pragma unroll
    for (int i = 0; i < 2; i++) {
        #pragma unroll
        for (int j = 0; j < 8; j++) {
            const int row = cRow * BM + wm * 32 + i * 16 + g;
            const int col = cCol * BN + wn * 64 + j * 8 + 2 * c;
            const float bx = bias[col];
            const float by = bias[col + 1];
            float2 v0 = make_float2(acc[i][j][0] + bx, acc[i][j][1] + by);
            float2 v1 = make_float2(acc[i][j][2] + bx, acc[i][j][3] + by);
            *(float2*)&C[(size_t)row * N + col]       = v0;
            *(float2*)&C[(size_t)(row + 8) * N + col] = v1;
        }
    }
}

// ---------------------------------------------------------------------------
// Fused conv(4) + SiLU + chunked EMA scan + gating.
// CHUNK=256, WARM=128, blockDim=128 -> 768 CTAs.
// Output stored tf32-rounded (bitwise identical to in-GEMM cvt).
// ---------------------------------------------------------------------------
__device__ __forceinline__ float silu_f(float v) {
    return v / (1.0f + __expf(-v));
}

__global__ __launch_bounds__(128)
void conv_scan_gate(const float* __restrict__ conv_w,
                    const float* __restrict__ conv_b,
                    const float* __restrict__ D_param)
{
    const int c  = blockIdx.x * blockDim.x + threadIdx.x;
    const int t0 = blockIdx.y * CHUNK;
    const int b  = blockIdx.z;
    int ts = t0 - WARM; if (ts < 0) ts = 0;

    const float w0 = conv_w[c * 4 + 0];
    const float w1 = conv_w[c * 4 + 1];
    const float w2 = conv_w[c * 4 + 2];
    const float w3 = conv_w[c * 4 + 3];
    const float cb = conv_b[c];
    const float Dp = D_param[c];

    const float* xin = g_xz + (size_t)b * TLEN * N1 + c;
    const float* zin = xin + DIN;
    float*       yo  = g_y  + (size_t)b * TLEN * DIN + c;

    float xm3 = (ts - 3 >= 0) ? xin[(size_t)(ts - 3) * N1] : 0.0f;
    float xm2 = (ts - 2 >= 0) ? xin[(size_t)(ts - 2) * N1] : 0.0f;
    float xm1 = (ts - 1 >= 0) ? xin[(size_t)(ts - 1) * N1] : 0.0f;

    float h = 0.0f;
    const int tend = t0 + CHUNK;
    #pragma unroll 4
    for (int t = ts; t < tend; t++) {
        const float xt   = xin[(size_t)t * N1];
        const float conv = fmaf(w0, xm3, fmaf(w1, xm2, fmaf(w2, xm1, fmaf(w3, xt, cb))));
        const float sc   = silu_f(conv);
        h = fmaf(0.9f, h, 0.1f * sc);
        if (t >= t0) {
            const float zv = zin[(size_t)t * N1];
            const float yv = fmaf(sc, Dp, h) * silu_f(zv);
            yo[(size_t)t * DIN] = __uint_as_float(f2tf(yv));
        }
        xm3 = xm2; xm2 = xm1; xm1 = xt;
    }
}

// ---------------------------------------------------------------------------
// Launch
// ---------------------------------------------------------------------------
extern "C" void kernel_launch(void* const* d_in, const int* in_sizes, int n_in,
                              void* d_out, int out_size)
{
    (void)in_sizes; (void)n_in; (void)out_size;

    const float* x       = (const float*)d_in[0];
    const float* in_w    = (const float*)d_in[1];
    const float* in_b    = (const float*)d_in[2];
    const float* conv_w  = (const float*)d_in[3];
    const float* conv_b  = (const float*)d_in[4];
    const float* D_param = (const float*)d_in[9];
    const float* out_w   = (const float*)d_in[10];
    const float* out_b   = (const float*)d_in[11];
    float*       out     = (float*)d_out;

    float *xz, *ya, *xr, *w1t, *w2t;
    cudaGetSymbolAddress((void**)&xz,  g_xz);
    cudaGetSymbolAddress((void**)&ya,  g_y);
    cudaGetSymbolAddress((void**)&xr,  g_xr);
    cudaGetSymbolAddress((void**)&w1t, g_w1t);
    cudaGetSymbolAddress((void**)&w2t, g_w2t);

    static bool attr_set = false;
    const int smem_bytes = SMEM_FLOATS * (int)sizeof(float);  // 73728
    if (!attr_set) {
        cudaFuncSetAttribute(tf32_gemm_bias,
                             cudaFuncAttributeMaxDynamicSharedMemorySize, smem_bytes);
        attr_set = true;
    }

    // Prepass: round x; transpose+round weights
    {
        int n4 = (M_ROWS * DMODEL) / 4;
        round_tf32<<<(n4 + 255) / 256, 256>>>((const float4*)x, (float4*)xr, n4);

        dim3 blk(32, 8);
        transpose_round<<<dim3(N1 / 32, DMODEL / 32), blk>>>(in_w,  w1t, DMODEL, N1);
        transpose_round<<<dim3(DMODEL / 32, DIN / 32), blk>>>(out_w, w2t, DIN, DMODEL);
    }

    // GEMM1: xz[16384,3072] = xr @ in_w + in_b   (B passed as w1t[N][K])
    {
        dim3 grid(N1 / BN, M_ROWS / BM);
        tf32_gemm_bias<<<grid, 256, smem_bytes>>>(M_ROWS, N1, DMODEL, xr, w1t, in_b, xz);
    }

    // Fused conv + silu + EMA scan + gate -> g_y (tf32-rounded)
    {
        dim3 grid(DIN / 128, TLEN / CHUNK, BATCH);
        conv_scan_gate<<<grid, 128>>>(conv_w, conv_b, D_param);
    }

    // GEMM2: out[16384,768] = y @ out_w + out_b  (B passed as w2t[N][K])
    {
        dim3 grid(DMODEL / BN, M_ROWS / BM);
        tf32_gemm_bias<<<grid, 256, smem_bytes>>>(M_ROWS, DMODEL, DIN, ya, w2t, out_b, out);
    }
}

// round 10
// speedup vs baseline: 4.2214x; 1.1472x over previous
#include <cuda_runtime.h>
#include <cuda_bf16.h>
#include <cstdint>

// ---------------------------------------------------------------------------
// Problem constants
// ---------------------------------------------------------------------------
#define BATCH    2
#define TLEN     8192
#define DMODEL   768
#define DIN      1536
#define M_ROWS   (BATCH * TLEN)   // 16384
#define N1       (2 * DIN)        // 3072
#define CHUNK    128
#define WARM     128              // 0.9^128 ~ 1.4e-6 -> exact at 1e-3 tol

// ---------------------------------------------------------------------------
// Scratch (__device__ globals; no allocation allowed)
// ---------------------------------------------------------------------------
__device__ float g_xz [(size_t)M_ROWS * N1];      // [16384, 3072]  x_inner | z
__device__ float g_y  [(size_t)M_ROWS * DIN];     // [16384, 1536]  (tf32-rounded)
__device__ float g_xr [(size_t)M_ROWS * DMODEL];  // x pre-rounded to tf32
__device__ float g_w1t[(size_t)N1 * DMODEL];      // in_w^T  [3072][768], tf32-rounded
__device__ float g_w2t[(size_t)DMODEL * DIN];     // out_w^T [768][1536], tf32-rounded

__device__ __forceinline__ uint32_t f2tf(float v) {
    uint32_t r;
    asm("cvt.rna.tf32.f32 %0, %1;" : "=r"(r) : "f"(v));
    return r;
}

// ---------------------------------------------------------------------------
// Prepass 1: elementwise tf32 rounding (for x)
// ---------------------------------------------------------------------------
__global__ __launch_bounds__(256)
void round_tf32(const float4* __restrict__ in, float4* __restrict__ out, int n4)
{
    int i = blockIdx.x * blockDim.x + threadIdx.x;
    if (i < n4) {
        float4 v = in[i];
        v.x = __uint_as_float(f2tf(v.x));
        v.y = __uint_as_float(f2tf(v.y));
        v.z = __uint_as_float(f2tf(v.z));
        v.w = __uint_as_float(f2tf(v.w));
        out[i] = v;
    }
}

// ---------------------------------------------------------------------------
// Prepass 2: transpose + tf32 round.  in[R][C] -> out[C][R]
// ---------------------------------------------------------------------------
__global__ __launch_bounds__(256)
void transpose_round(const float* __restrict__ in, float* __restrict__ out,
                     int R, int C)
{
    __shared__ float t[32][33];
    const int bx = blockIdx.x * 32;
    const int by = blockIdx.y * 32;
    const int tx = threadIdx.x, ty = threadIdx.y;

    #pragma unroll
    for (int dy = 0; dy < 32; dy += 8)
        t[ty + dy][tx] = in[(size_t)(by + ty + dy) * C + bx + tx];
    __syncthreads();
    #pragma unroll
    for (int dy = 0; dy < 32; dy += 8)
        out[(size_t)(bx + ty + dy) * R + by + tx] =
            __uint_as_float(f2tf(t[tx][ty + dy]));
}

// ---------------------------------------------------------------------------
// TF32 tensor-core GEMM, ldmatrix fragments, single-barrier pipelined loop.
//   C[M,N] = A[M,K] @ B[K,N] + bias[N],  B passed TRANSPOSED as BT[N][K].
// 128x128x32 CTA tile, 256 thr (4x2 warps, 32x64 warp tiles),
// mma.sync.m16n8k8.tf32, cp.async double-buffered.
// Loop order per iter: wait -> sync -> issue next stage -> compute.
// ---------------------------------------------------------------------------
#define BM 128
#define BN 128
#define BK 32
#define BKP 36
#define AS_SZ (BM * BKP)
#define BS_SZ (BN * BKP)
#define BS_OFF (2 * AS_SZ)
#define SMEM_FLOATS (2 * AS_SZ + 2 * BS_SZ)   // 73728 B
#define AS_SZB (AS_SZ * 4)
#define BS_SZB (BS_SZ * 4)
#define BS_OFFB (BS_OFF * 4)
#define ROWB (BKP * 4)

__device__ __forceinline__ void cp16(float* smem_ptr, const float* g) {
    uint32_t a = (uint32_t)__cvta_generic_to_shared(smem_ptr);
    asm volatile("cp.async.cg.shared.global [%0], [%1], 16;" :: "r"(a), "l"(g));
}
__device__ __forceinline__ void ldsm4(uint32_t& r0, uint32_t& r1,
                                      uint32_t& r2, uint32_t& r3, uint32_t addr) {
    asm volatile("ldmatrix.sync.aligned.m8n8.x4.shared.b16 {%0,%1,%2,%3}, [%4];"
                 : "=r"(r0), "=r"(r1), "=r"(r2), "=r"(r3) : "r"(addr));
}

__global__ __launch_bounds__(256, 2)
void tf32_gemm_bias(int M, int N, int K,
                    const float* __restrict__ A,
                    const float* __restrict__ BT,
                    const float* __restrict__ bias,
                    float* __restrict__ C)
{
    extern __shared__ float sm[];

    const int tid  = threadIdx.x;
    const int lane = tid & 31;
    const int wid  = tid >> 5;
    const int g    = lane >> 2;
    const int c    = lane & 3;
    const int wm   = wid & 3;
    const int wn   = wid >> 2;

    const int cRow = blockIdx.y;
    const int cCol = blockIdx.x;
    const float* Ab = A  + (size_t)cRow * BM * K;
    const float* Bb = BT + (size_t)cCol * BN * K;

    const int aR = tid >> 3;           // 0..31
    const int aK = (tid & 7) * 4;      // 0..28

    const uint32_t smem_u = (uint32_t)__cvta_generic_to_shared(sm);
    const uint32_t a_off = (uint32_t)((wm * 32 + (lane & 15)) * ROWB + (lane >> 4) * 16);
    const uint32_t b_off = (uint32_t)((wn * 64 + ((lane & 7) + ((lane >> 4) << 3))) * ROWB
                                      + (((lane >> 3) & 1) << 4));

    float acc[2][8][4];
    #pragma unroll
    for (int i = 0; i < 2; i++)
        #pragma unroll
        for (int j = 0; j < 8; j++)
            #pragma unroll
            for (int q = 0; q < 4; q++) acc[i][j][q] = 0.0f;

    const int iters = K / BK;

    {   // prologue: stage 0
        #pragma unroll
        for (int p = 0; p < 4; p++) {
            const int row = p * 32 + aR;
            cp16(&sm[row * BKP + aK],          Ab + (size_t)row * K + aK);
            cp16(&sm[BS_OFF + row * BKP + aK], Bb + (size_t)row * K + aK);
        }
        asm volatile("cp.async.commit_group;");
    }

    for (int it = 0; it < iters; it++) {
        const int buf = it & 1;

        // stage `it` resident; all warps past their reads of buf^1
        asm volatile("cp.async.wait_group 0;");
        __syncthreads();

        // issue next stage into buf^1 (overlaps with compute below)
        if (it + 1 < iters) {
            const int k0 = (it + 1) * BK;
            const int nb = buf ^ 1;
            #pragma unroll
            for (int p = 0; p < 4; p++) {
                const int row = p * 32 + aR;
                cp16(&sm[nb * AS_SZ + row * BKP + aK],
                     Ab + (size_t)row * K + k0 + aK);
                cp16(&sm[BS_OFF + nb * BS_SZ + row * BKP + aK],
                     Bb + (size_t)row * K + k0 + aK);
            }
            asm volatile("cp.async.commit_group;");
        }

        const uint32_t aBase = smem_u + (uint32_t)buf * AS_SZB + a_off;
        const uint32_t bBase = smem_u + BS_OFFB + (uint32_t)buf * BS_SZB + b_off;

        #pragma unroll
        for (int ks = 0; ks < 4; ks++) {
            const uint32_t kb = (uint32_t)ks * 32;

            uint32_t af[2][4];
            ldsm4(af[0][0], af[0][1], af[0][2], af[0][3], aBase + kb);
            ldsm4(af[1][0], af[1][1], af[1][2], af[1][3], aBase + 16 * ROWB + kb);

            uint32_t bf[8][2];
            #pragma unroll
            for (int j2 = 0; j2 < 4; j2++) {
                uint32_t r0, r1, r2, r3;
                ldsm4(r0, r1, r2, r3, bBase + (uint32_t)j2 * 16 * ROWB + kb);
                bf[2 * j2][0]     = r0;  bf[2 * j2][1]     = r1;
                bf[2 * j2 + 1][0] = r2;  bf[2 * j2 + 1][1] = r3;
            }

            #pragma unroll
            for (int i = 0; i < 2; i++)
                #pragma unroll
                for (int j = 0; j < 8; j++) {
                    asm volatile(
                        "mma.sync.aligned.m16n8k8.row.col.f32.tf32.tf32.f32 "
                        "{%0,%1,%2,%3}, {%4,%5,%6,%7}, {%8,%9}, {%0,%1,%2,%3};"
                        : "+f"(acc[i][j][0]), "+f"(acc[i][j][1]),
                          "+f"(acc[i][j][2]), "+f"(acc[i][j][3])
                        : "r"(af[i][0]), "r"(af[i][1]), "r"(af[i][2]), "r"(af[i][3]),
                          "r"(bf[j][0]), "r"(bf[j][1]));
                }
        }
    }

    // epilogue: bias + store
    #pragma unroll
    for (int i = 0; i < 2; i++) {
        #pragma unroll
        for (int j = 0; j < 8; j++) {
            const int row = cRow * BM + wm * 32 + i * 16 + g;
            const int col = cCol * BN + wn * 64 + j * 8 + 2 * c;
            const float bx = bias[col];
            const float by = bias[col + 1];
            float2 v0 = make_float2(acc[i][j][0] + bx, acc[i][j][1] + by);
            float2 v1 = make_float2(acc[i][j][2] + bx, acc[i][j][3] + by);
            *(float2*)&C[(size_t)row * N + col]       = v0;
            *(float2*)&C[(size_t)(row + 8) * N + col] = v1;
        }
    }
}

// ---------------------------------------------------------------------------
// Fused conv(4) + SiLU + chunked EMA scan + gating.
// CHUNK=128, WARM=128, blockDim=128 -> 1536 CTAs (~41 warps/SM).
// Output stored tf32-rounded (bitwise identical to in-GEMM cvt).
// ---------------------------------------------------------------------------
__device__ __forceinline__ float silu_f(float v) {
    return v / (1.0f + __expf(-v));
}

__global__ __launch_bounds__(128)
void conv_scan_gate(const float* __restrict__ conv_w,
                    const float* __restrict__ conv_b,
                    const float* __restrict__ D_param)
{
    const int c  = blockIdx.x * blockDim.x + threadIdx.x;
    const int t0 = blockIdx.y * CHUNK;
    const int b  = blockIdx.z;
    int ts = t0 - WARM; if (ts < 0) ts = 0;

    const float w0 = conv_w[c * 4 + 0];
    const float w1 = conv_w[c * 4 + 1];
    const float w2 = conv_w[c * 4 + 2];
    const float w3 = conv_w[c * 4 + 3];
    const float cb = conv_b[c];
    const float Dp = D_param[c];

    const float* xin = g_xz + (size_t)b * TLEN * N1 + c;
    const float* zin = xin + DIN;
    float*       yo  = g_y  + (size_t)b * TLEN * DIN + c;

    float xm3 = (ts - 3 >= 0) ? xin[(size_t)(ts - 3) * N1] : 0.0f;
    float xm2 = (ts - 2 >= 0) ? xin[(size_t)(ts - 2) * N1] : 0.0f;
    float xm1 = (ts - 1 >= 0) ? xin[(size_t)(ts - 1) * N1] : 0.0f;

    float h = 0.0f;
    const int tend = t0 + CHUNK;
    #pragma unroll 8
    for (int t = ts; t < tend; t++) {
        const float xt   = xin[(size_t)t * N1];
        const float conv = fmaf(w0, xm3, fmaf(w1, xm2, fmaf(w2, xm1, fmaf(w3, xt, cb))));
        const float sc   = silu_f(conv);
        h = fmaf(0.9f, h, 0.1f * sc);
        if (t >= t0) {
            const float zv = zin[(size_t)t * N1];
            const float yv = fmaf(sc, Dp, h) * silu_f(zv);
            yo[(size_t)t * DIN] = __uint_as_float(f2tf(yv));
        }
        xm3 = xm2; xm2 = xm1; xm1 = xt;
    }
}

// ---------------------------------------------------------------------------
// Launch
// ---------------------------------------------------------------------------
extern "C" void kernel_launch(void* const* d_in, const int* in_sizes, int n_in,
                              void* d_out, int out_size)
{
    (void)in_sizes; (void)n_in; (void)out_size;

    const float* x       = (const float*)d_in[0];
    const float* in_w    = (const float*)d_in[1];
    const float* in_b    = (const float*)d_in[2];
    const float* conv_w  = (const float*)d_in[3];
    const float* conv_b  = (const float*)d_in[4];
    const float* D_param = (const float*)d_in[9];
    const float* out_w   = (const float*)d_in[10];
    const float* out_b   = (const float*)d_in[11];
    float*       out     = (float*)d_out;

    float *xz, *ya, *xr, *w1t, *w2t;
    cudaGetSymbolAddress((void**)&xz,  g_xz);
    cudaGetSymbolAddress((void**)&ya,  g_y);
    cudaGetSymbolAddress((void**)&xr,  g_xr);
    cudaGetSymbolAddress((void**)&w1t, g_w1t);
    cudaGetSymbolAddress((void**)&w2t, g_w2t);

    static bool attr_set = false;
    const int smem_bytes = SMEM_FLOATS * (int)sizeof(float);  // 73728
    if (!attr_set) {
        cudaFuncSetAttribute(tf32_gemm_bias,
                             cudaFuncAttributeMaxDynamicSharedMemorySize, smem_bytes);
        attr_set = true;
    }

    // Prepass: round x; transpose+round weights
    {
        int n4 = (M_ROWS * DMODEL) / 4;
        round_tf32<<<(n4 + 255) / 256, 256>>>((const float4*)x, (float4*)xr, n4);

        dim3 blk(32, 8);
        transpose_round<<<dim3(N1 / 32, DMODEL / 32), blk>>>(in_w,  w1t, DMODEL, N1);
        transpose_round<<<dim3(DMODEL / 32, DIN / 32), blk>>>(out_w, w2t, DIN, DMODEL);
    }

    // GEMM1: xz[16384,3072] = xr @ in_w + in_b   (B passed as w1t[N][K])
    {
        dim3 grid(N1 / BN, M_ROWS / BM);
        tf32_gemm_bias<<<grid, 256, smem_bytes>>>(M_ROWS, N1, DMODEL, xr, w1t, in_b, xz);
    }

    // Fused conv + silu + EMA scan + gate -> g_y (tf32-rounded)
    {
        dim3 grid(DIN / 128, TLEN / CHUNK, BATCH);
        conv_scan_gate<<<grid, 128>>>(conv_w, conv_b, D_param);
    }

    // GEMM2: out[16384,768] = y @ out_w + out_b  (B passed as w2t[N][K])
    {
        dim3 grid(DMODEL / BN, M_ROWS / BM);
        tf32_gemm_bias<<<grid, 256, smem_bytes>>>(M_ROWS, DMODEL, DIN, ya, w2t, out_b, out);
    }
}